// round 14
// baseline (speedup 1.0000x reference)
#include <cuda_runtime.h>

#define BB   4
#define NA   2048
#define NBB  2048
#define HH   8
#define NSPLIT 4
#define BN   (BB * NA)
#define LOG2E 1.44269504088896340736f

typedef unsigned long long ull;

#define FMA2(d, a, b) asm("fma.rn.f32x2 %0, %1, %2, %0;" : "+l"(d) : "l"(a), "l"(b))
#define PACK2(d, lo, hi) asm("mov.b64 %0, {%1, %2};" : "=l"(d) : "f"(lo), "f"(hi))
#define UNPACK2(lo, hi, s) asm("mov.b64 {%0, %1}, %2;" : "=f"(lo), "=f"(hi) : "l"(s))

// ---------------- scratch (static device allocs only) ----------------
__device__ float  g_zB[BB * NBB * 128];       // (b, m, h*16+d)
__device__ float4 g_eAp[BB * NA * HH];        // (ea, 2^ea, 2^.01ea, 0), log2-scaled
__device__ float4 g_eBp[BB * HH * NBB];       // [(b*8+h)*2048+m] = (eb, 2^eb, 2^.01eb, 0)
__device__ float  g_WT[128 * 128];            // W_T[c*128+o]
__device__ float  g_Pacc[NSPLIT * BN * HH * 16];   // [s][(b*2048+n)][h][16]
__device__ float  g_PZ[NSPLIT * BN * HH];          // [s][(b*2048+n)*8+h]

// ---------------- K1: eA/eB + exp factors; CTAs >= 512 transpose W ----------------
__global__ __launch_bounds__(256)
void k_e(const float* __restrict__ hA, const float* __restrict__ hB,
         const float* __restrict__ WA_w, const float* __restrict__ WA_b,
         const float* __restrict__ aA_w, const float* __restrict__ aA_b,
         const float* __restrict__ WB_w, const float* __restrict__ WB_b,
         const float* __restrict__ aB_w, const float* __restrict__ aB_b,
         const float* __restrict__ W_w) {
    int t = threadIdx.x;
    int bx = blockIdx.x;
    if (bx >= 512) {                          // W transpose (64 CTAs)
        int idx = (bx - 512) * 256 + t;
        int o = idx >> 7, c = idx & 127;
        g_WT[c * 128 + o] = W_w[idx];
        return;
    }

    __shared__ float vs[HH * 128];
    __shared__ float ccs[HH];
    bool isA = bx < 256;
    const float* x  = isA ? hA : hB;
    const float* Ww = isA ? WA_w : WB_w;
    const float* Wb = isA ? WA_b : WB_b;
    const float* aw = isA ? aA_w : aB_w;
    const float* ab = isA ? aA_b : aB_b;

    #pragma unroll
    for (int j = 0; j < 4; j++) {
        int idx = t + j * 256;                // (h,i)
        int h = idx >> 7, i = idx & 127;
        float s = 0.f;
        #pragma unroll
        for (int d = 0; d < 16; d++)
            s += Ww[(h * 128 + i) * 16 + d] * aw[h * 16 + d];
        vs[idx] = s;
    }
    if (t < HH) {
        float c = ab[t];
        #pragma unroll
        for (int d = 0; d < 16; d++)
            c += Wb[t * 16 + d] * aw[t * 16 + d];
        ccs[t] = c;
    }
    __syncthreads();

    int li = (bx & 255) * 256 + t;            // 0..65535
    int h = li & 7;
    int row = li >> 3;                        // b*2048 + (n or m)
    const float4* xr = (const float4*)(x + (size_t)row * 128);
    const float4* vr = (const float4*)(vs + h * 128);
    float e = ccs[h];
    #pragma unroll
    for (int q = 0; q < 32; q++) {
        float4 a = xr[q], b = vr[q];
        e += a.x * b.x + a.y * b.y + a.z * b.z + a.w * b.w;
    }
    e *= LOG2E;
    float p0, p1, es = 0.01f * e;
    asm("ex2.approx.f32 %0, %1;" : "=f"(p0) : "f"(e));
    asm("ex2.approx.f32 %0, %1;" : "=f"(p1) : "f"(es));
    if (isA) {
        g_eAp[li] = make_float4(e, p0, p1, 0.f);
    } else {
        int b = row >> 11, m = row & 2047;
        g_eBp[((b * 8 + h) << 11) + m] = make_float4(e, p0, p1, 0.f);
    }
}

// ---------------- K2: z_B = h_B @ Wc + bias ----------------
#define ZB_SMEM ((128 * 128 + 32 * 128) * 4)   // 80 KB
__global__ __launch_bounds__(256, 2)
void k_zB(const float* __restrict__ hB, const float* __restrict__ WB_w,
          const float* __restrict__ WB_b) {
    extern __shared__ float sm[];
    float* Wc = sm;                 // [i*128 + (h*16+d)]
    float* xs = sm + 128 * 128;     // [r*128 + i]
    int t = threadIdx.x;
    int row0 = blockIdx.x * 32;

    for (int idx = t; idx < 16384; idx += 256) {
        int h = idx >> 11, i = (idx >> 4) & 127, d = idx & 15;
        Wc[i * 128 + h * 16 + d] = WB_w[idx];
    }
    {
        const float4* src = (const float4*)(hB + (size_t)row0 * 128);
        #pragma unroll
        for (int j = 0; j < 4; j++)
            ((float4*)xs)[t + j * 256] = src[t + j * 256];
    }
    __syncthreads();

    int c = t & 127, rg = t >> 7;
    float acc[16];
    #pragma unroll
    for (int k = 0; k < 16; k++) acc[k] = 0.f;

    for (int i = 0; i < 128; i += 4) {
        float w0 = Wc[i * 128 + c];
        float w1 = Wc[(i + 1) * 128 + c];
        float w2 = Wc[(i + 2) * 128 + c];
        float w3 = Wc[(i + 3) * 128 + c];
        #pragma unroll
        for (int k = 0; k < 16; k++) {
            int r = rg * 16 + k;
            float4 x4 = *(const float4*)&xs[r * 128 + i];
            acc[k] += x4.x * w0 + x4.y * w1 + x4.z * w2 + x4.w * w3;
        }
    }
    float bias = WB_b[c];
    #pragma unroll
    for (int k = 0; k < 16; k++) {
        int r = rg * 16 + k;
        g_zB[(size_t)(row0 + r) * 128 + c] = acc[k] + bias;
    }
}

// ---------------- K4: partial masked softmax-attention (m-split by 4) ----------------
// CTA = 64 rows x 8 heads, 256 threads; warp = head, each thread 2 rows.
// grid.x = 128: tile = x>>2 (n-tile of 64, 32 tiles), s = x&3 (m quarter). grid.y = b.
#define MAIN_SMEM ((8192 + 2048) * 4 + 64 * 8)
__global__ __launch_bounds__(256, 2)
void k_main(const int* __restrict__ mask) {
    extern __shared__ float sm[];
    float*  zB_s  = sm;                       // 8192 f
    float4* eBp_s = (float4*)(sm + 8192);     // 512 float4: [h][64]
    ull*    mp_s  = (ull*)(sm + 8192 + 2048); // 64

    int t = threadIdx.x;
    int lane = t & 31;                        // row within tile (and +32)
    int h = t >> 5;                           // head
    int b = blockIdx.y;
    int tile = blockIdx.x >> 2;
    int s = blockIdx.x & 3;
    int n0 = tile * 64;
    int row0 = b * NA + n0;
    int mlo = s * (NBB / NSPLIT);             // 512-wide m range

    float4 pa0 = g_eAp[(size_t)(row0 + lane) * 8 + h];      // (ea, p0, p1, -)
    float4 pa1 = g_eAp[(size_t)(row0 + lane + 32) * 8 + h];
    float nea0 = -pa0.x, pA00 = pa0.y, pA01 = pa0.z;        // sign test: eb >= -ea
    float nea1 = -pa1.x, pA10 = pa1.y, pA11 = pa1.z;

    ull acc0[8], acc1[8];
    #pragma unroll
    for (int k = 0; k < 8; k++) { acc0[k] = 0ULL; acc1[k] = 0ULL; }
    ull accZ = 0ULL;                          // packed (Z0, Z1)
    const ull ONES2 = 0x3F8000003F800000ULL;  // (1.0f, 1.0f)

    const float4* eBbase = g_eBp + ((size_t)b * 8) * 2048;  // + h*2048 + m

    for (int m0 = mlo; m0 < mlo + NBB / NSPLIT; m0 += 64) {
        __syncthreads();
        // stage zB tile (64 rows x 128 f = 2048 float4), 8 per thread
        {
            const float4* src = (const float4*)(g_zB + (size_t)(b * NBB + m0) * 128);
            #pragma unroll
            for (int j = 0; j < 8; j++)
                ((float4*)zB_s)[t + j * 256] = src[t + j * 256];
        }
        // stage eBp tile: [h][64] float4, 2 per thread
        {
            int hh = t >> 6, mm = t & 63;
            eBp_s[hh * 64 + mm]       = eBbase[(size_t)hh * 2048 + m0 + mm];
            eBp_s[(hh + 4) * 64 + mm] = eBbase[(size_t)(hh + 4) * 2048 + m0 + mm];
        }
        // pack mask (int32 0/1): 64 rows x 64 bits = 512 bytes, 2 per thread
        {
            #pragma unroll
            for (int j = 0; j < 2; j++) {
                int idx = t + j * 256;
                int rowi = idx >> 3, bytei = idx & 7;
                const int4* mp4 = (const int4*)
                    (mask + ((size_t)(row0 + rowi)) * NBB + m0 + bytei * 8);
                int4 a = mp4[0], c = mp4[1];
                unsigned int bits =
                      (unsigned int)(a.x != 0)
                    | ((unsigned int)(a.y != 0) << 1)
                    | ((unsigned int)(a.z != 0) << 2)
                    | ((unsigned int)(a.w != 0) << 3)
                    | ((unsigned int)(c.x != 0) << 4)
                    | ((unsigned int)(c.y != 0) << 5)
                    | ((unsigned int)(c.z != 0) << 6)
                    | ((unsigned int)(c.w != 0) << 7);
                ((unsigned char*)mp_s)[rowi * 8 + bytei] = (unsigned char)bits;
            }
        }
        __syncthreads();

        ull mb0 = mp_s[lane];
        ull mb1 = mp_s[lane + 32];
        const float4* ebh = eBp_s + h * 64;
        #pragma unroll 8
        for (int m = 0; m < 64; m++) {
            float4 eb = ebh[m];                         // (eb, pB0, pB1, -)
            float w0 = (eb.x >= nea0) ? (pA00 * eb.y) : (pA01 * eb.z);
            float w1 = (eb.x >= nea1) ? (pA10 * eb.y) : (pA11 * eb.z);
            w0 = ((mb0 >> m) & 1ULL) ? w0 : 0.f;
            w1 = ((mb1 >> m) & 1ULL) ? w1 : 0.f;
            ull wz, wd0, wd1;
            PACK2(wz, w0, w1);
            FMA2(accZ, wz, ONES2);                      // Z0 += w0, Z1 += w1
            PACK2(wd0, w0, w0);
            PACK2(wd1, w1, w1);
            const ulonglong2* z = (const ulonglong2*)(zB_s + m * 128 + h * 16);
            ulonglong2 q0 = z[0], q1 = z[1], q2 = z[2], q3 = z[3];
            FMA2(acc0[0], wd0, q0.x); FMA2(acc0[1], wd0, q0.y);
            FMA2(acc0[2], wd0, q1.x); FMA2(acc0[3], wd0, q1.y);
            FMA2(acc0[4], wd0, q2.x); FMA2(acc0[5], wd0, q2.y);
            FMA2(acc0[6], wd0, q3.x); FMA2(acc0[7], wd0, q3.y);
            FMA2(acc1[0], wd1, q0.x); FMA2(acc1[1], wd1, q0.y);
            FMA2(acc1[2], wd1, q1.x); FMA2(acc1[3], wd1, q1.y);
            FMA2(acc1[4], wd1, q2.x); FMA2(acc1[5], wd1, q2.y);
            FMA2(acc1[6], wd1, q3.x); FMA2(acc1[7], wd1, q3.y);
        }
    }

    // write partials: [s][(b*2048+n)][h][16] and Z
    {
        float Z0, Z1;
        UNPACK2(Z0, Z1, accZ);
        size_t base0 = ((size_t)s * BN + row0 + lane) * 8 + h;
        size_t base1 = ((size_t)s * BN + row0 + lane + 32) * 8 + h;
        float4* p0 = (float4*)(g_Pacc + base0 * 16);
        float4* p1 = (float4*)(g_Pacc + base1 * 16);
        #pragma unroll
        for (int k = 0; k < 4; k++) {
            float a, bq, c, d;
            UNPACK2(a, bq, acc0[2 * k]);
            UNPACK2(c, d, acc0[2 * k + 1]);
            p0[k] = make_float4(a, bq, c, d);
            UNPACK2(a, bq, acc1[2 * k]);
            UNPACK2(c, d, acc1[2 * k + 1]);
            p1[k] = make_float4(a, bq, c, d);
        }
        g_PZ[base0] = Z0;
        g_PZ[base1] = Z1;
    }
}

// ---------------- K5: combine partials + normalize + output GEMM ----------------
// CTA = 32 rows x 8 heads = 256 threads; grid (64, 4)
#define RED_SMEM ((16384 + 32 * 129) * 4)
__global__ __launch_bounds__(256)
void k_reduce(const float* __restrict__ W_b, float* __restrict__ out) {
    extern __shared__ float rsm[];
    float* W_Ts = rsm;                  // 16384
    float* cat_s = rsm + 16384;         // 32*129
    int t = threadIdx.x;
    int lane = t & 31;
    int h = t >> 5;
    int b = blockIdx.y;
    int n0 = blockIdx.x * 32;
    int row = b * NA + n0 + lane;

    #pragma unroll
    for (int j = 0; j < 16; j++)
        ((float4*)W_Ts)[t + j * 256] = ((const float4*)g_WT)[t + j * 256];

    {
        float v[16];
        #pragma unroll
        for (int k = 0; k < 16; k++) v[k] = 0.f;
        float Z = 0.f;
        #pragma unroll
        for (int sp = 0; sp < NSPLIT; sp++) {
            const float4* p = (const float4*)
                (g_Pacc + (((size_t)sp * BN + row) * 8 + h) * 16);
            #pragma unroll
            for (int k = 0; k < 4; k++) {
                float4 a = p[k];
                v[4 * k]     += a.x;
                v[4 * k + 1] += a.y;
                v[4 * k + 2] += a.z;
                v[4 * k + 3] += a.w;
            }
            Z += g_PZ[((size_t)sp * BN + row) * 8 + h];
        }
        float inv = 1.f / Z;
        #pragma unroll
        for (int k = 0; k < 16; k++)
            cat_s[lane * 129 + h * 16 + k] = v[k] * inv;
    }
    __syncthreads();

    float acc2[16];
    {
        const float4* wb4 = (const float4*)(W_b + h * 16);
        float4 b0 = __ldg(wb4), b1 = __ldg(wb4 + 1), b2 = __ldg(wb4 + 2), b3 = __ldg(wb4 + 3);
        acc2[0]  = b0.x; acc2[1]  = b0.y; acc2[2]  = b0.z; acc2[3]  = b0.w;
        acc2[4]  = b1.x; acc2[5]  = b1.y; acc2[6]  = b1.z; acc2[7]  = b1.w;
        acc2[8]  = b2.x; acc2[9]  = b2.y; acc2[10] = b2.z; acc2[11] = b2.w;
        acc2[12] = b3.x; acc2[13] = b3.y; acc2[14] = b3.z; acc2[15] = b3.w;
    }
    for (int c = 0; c < 128; c++) {
        float x = cat_s[lane * 129 + c];
        const float4* w4 = (const float4*)(W_Ts + c * 128 + h * 16);
        float4 w0 = w4[0], w1 = w4[1], w2 = w4[2], w3 = w4[3];
        acc2[0]  += x * w0.x; acc2[1]  += x * w0.y; acc2[2]  += x * w0.z; acc2[3]  += x * w0.w;
        acc2[4]  += x * w1.x; acc2[5]  += x * w1.y; acc2[6]  += x * w1.z; acc2[7]  += x * w1.w;
        acc2[8]  += x * w2.x; acc2[9]  += x * w2.y; acc2[10] += x * w2.z; acc2[11] += x * w2.w;
        acc2[12] += x * w3.x; acc2[13] += x * w3.y; acc2[14] += x * w3.z; acc2[15] += x * w3.w;
    }
    float4* o4 = (float4*)(out + (size_t)row * 128 + h * 16);
    o4[0] = make_float4(acc2[0],  acc2[1],  acc2[2],  acc2[3]);
    o4[1] = make_float4(acc2[4],  acc2[5],  acc2[6],  acc2[7]);
    o4[2] = make_float4(acc2[8],  acc2[9],  acc2[10], acc2[11]);
    o4[3] = make_float4(acc2[12], acc2[13], acc2[14], acc2[15]);
}

// ---------------- launcher ----------------
extern "C" void kernel_launch(void* const* d_in, const int* in_sizes, int n_in,
                              void* d_out, int out_size) {
    (void)in_sizes; (void)n_in; (void)out_size;
    const float* h_A  = (const float*)d_in[0];
    const float* h_B  = (const float*)d_in[1];
    const int*   mask = (const int*)d_in[2];
    const float* WA_w = (const float*)d_in[3];
    const float* WA_b = (const float*)d_in[4];
    const float* WB_w = (const float*)d_in[5];
    const float* WB_b = (const float*)d_in[6];
    const float* aA_w = (const float*)d_in[7];
    const float* aA_b = (const float*)d_in[8];
    const float* aB_w = (const float*)d_in[9];
    const float* aB_b = (const float*)d_in[10];
    const float* W_w  = (const float*)d_in[11];
    const float* W_b  = (const float*)d_in[12];
    float* out = (float*)d_out;

    cudaFuncSetAttribute(k_zB,     cudaFuncAttributeMaxDynamicSharedMemorySize, ZB_SMEM);
    cudaFuncSetAttribute(k_main,   cudaFuncAttributeMaxDynamicSharedMemorySize, MAIN_SMEM);
    cudaFuncSetAttribute(k_reduce, cudaFuncAttributeMaxDynamicSharedMemorySize, RED_SMEM);

    k_e<<<576, 256>>>(h_A, h_B, WA_w, WA_b, aA_w, aA_b, WB_w, WB_b, aB_w, aB_b, W_w);
    k_zB<<<256, 256, ZB_SMEM>>>(h_B, WB_w, WB_b);
    k_main<<<dim3(32 * NSPLIT, 4), 256, MAIN_SMEM>>>(mask);
    k_reduce<<<dim3(64, 4), 256, RED_SMEM>>>(W_b, out);
}

// round 15
// speedup vs baseline: 1.1239x; 1.1239x over previous
#include <cuda_runtime.h>

#define BB   4
#define NA   2048
#define NBB  2048
#define HH   8
#define NSPLIT 8
#define BN   (BB * NA)
#define LOG2E 1.44269504088896340736f

typedef unsigned long long ull;

#define FMA2(d, a, b) asm("fma.rn.f32x2 %0, %1, %2, %0;" : "+l"(d) : "l"(a), "l"(b))
#define PACK2(d, lo, hi) asm("mov.b64 %0, {%1, %2};" : "=l"(d) : "f"(lo), "f"(hi))
#define UNPACK2(lo, hi, s) asm("mov.b64 {%0, %1}, %2;" : "=f"(lo), "=f"(hi) : "l"(s))

// ---------------- scratch (static device allocs only) ----------------
__device__ float  g_zB[BB * NBB * 128];       // (b, m, h*16+d)
__device__ float4 g_eAp[BB * NA * HH];        // (ea, 2^ea, 2^.01ea, 0), log2-scaled
__device__ float4 g_eBp[BB * HH * NBB];       // [(b*8+h)*2048+m] = (eb, 2^eb, 2^.01eb, 0)
__device__ float  g_WT[128 * 128];            // W_T[c*128+o]
__device__ ull    g_PaccU[NSPLIT * BB * HH * 8 * NA];  // [s][b][h][d2][n], packed (d=2k,2k+1)
__device__ float  g_PZ[NSPLIT * BB * HH * NA];         // [s][b][h][n]

// ---------------- K1: eA/eB + exp factors; CTAs >= 512 transpose W ----------------
__global__ __launch_bounds__(256)
void k_e(const float* __restrict__ hA, const float* __restrict__ hB,
         const float* __restrict__ WA_w, const float* __restrict__ WA_b,
         const float* __restrict__ aA_w, const float* __restrict__ aA_b,
         const float* __restrict__ WB_w, const float* __restrict__ WB_b,
         const float* __restrict__ aB_w, const float* __restrict__ aB_b,
         const float* __restrict__ W_w) {
    int t = threadIdx.x;
    int bx = blockIdx.x;
    if (bx >= 512) {                          // W transpose (64 CTAs)
        int idx = (bx - 512) * 256 + t;
        int o = idx >> 7, c = idx & 127;
        g_WT[c * 128 + o] = W_w[idx];
        return;
    }

    __shared__ float vs[HH * 128];
    __shared__ float ccs[HH];
    bool isA = bx < 256;
    const float* x  = isA ? hA : hB;
    const float* Ww = isA ? WA_w : WB_w;
    const float* Wb = isA ? WA_b : WB_b;
    const float* aw = isA ? aA_w : aB_w;
    const float* ab = isA ? aA_b : aB_b;

    #pragma unroll
    for (int j = 0; j < 4; j++) {
        int idx = t + j * 256;                // (h,i)
        int h = idx >> 7, i = idx & 127;
        float s = 0.f;
        #pragma unroll
        for (int d = 0; d < 16; d++)
            s += Ww[(h * 128 + i) * 16 + d] * aw[h * 16 + d];
        vs[idx] = s;
    }
    if (t < HH) {
        float c = ab[t];
        #pragma unroll
        for (int d = 0; d < 16; d++)
            c += Wb[t * 16 + d] * aw[t * 16 + d];
        ccs[t] = c;
    }
    __syncthreads();

    int li = (bx & 255) * 256 + t;            // 0..65535
    int h = li & 7;
    int row = li >> 3;                        // b*2048 + (n or m)
    const float4* xr = (const float4*)(x + (size_t)row * 128);
    const float4* vr = (const float4*)(vs + h * 128);
    float e = ccs[h];
    #pragma unroll
    for (int q = 0; q < 32; q++) {
        float4 a = xr[q], b = vr[q];
        e += a.x * b.x + a.y * b.y + a.z * b.z + a.w * b.w;
    }
    e *= LOG2E;
    float p0, p1, es = 0.01f * e;
    asm("ex2.approx.f32 %0, %1;" : "=f"(p0) : "f"(e));
    asm("ex2.approx.f32 %0, %1;" : "=f"(p1) : "f"(es));
    if (isA) {
        g_eAp[li] = make_float4(e, p0, p1, 0.f);
    } else {
        int b = row >> 11, m = row & 2047;
        g_eBp[((b * 8 + h) << 11) + m] = make_float4(e, p0, p1, 0.f);
    }
}

// ---------------- K2: z_B = h_B @ Wc + bias ----------------
#define ZB_SMEM ((128 * 128 + 32 * 128) * 4)   // 80 KB
__global__ __launch_bounds__(256, 2)
void k_zB(const float* __restrict__ hB, const float* __restrict__ WB_w,
          const float* __restrict__ WB_b) {
    extern __shared__ float sm[];
    float* Wc = sm;                 // [i*128 + (h*16+d)]
    float* xs = sm + 128 * 128;     // [r*128 + i]
    int t = threadIdx.x;
    int row0 = blockIdx.x * 32;

    for (int idx = t; idx < 16384; idx += 256) {
        int h = idx >> 11, i = (idx >> 4) & 127, d = idx & 15;
        Wc[i * 128 + h * 16 + d] = WB_w[idx];
    }
    {
        const float4* src = (const float4*)(hB + (size_t)row0 * 128);
        #pragma unroll
        for (int j = 0; j < 4; j++)
            ((float4*)xs)[t + j * 256] = src[t + j * 256];
    }
    __syncthreads();

    int c = t & 127, rg = t >> 7;
    float acc[16];
    #pragma unroll
    for (int k = 0; k < 16; k++) acc[k] = 0.f;

    for (int i = 0; i < 128; i += 4) {
        float w0 = Wc[i * 128 + c];
        float w1 = Wc[(i + 1) * 128 + c];
        float w2 = Wc[(i + 2) * 128 + c];
        float w3 = Wc[(i + 3) * 128 + c];
        #pragma unroll
        for (int k = 0; k < 16; k++) {
            int r = rg * 16 + k;
            float4 x4 = *(const float4*)&xs[r * 128 + i];
            acc[k] += x4.x * w0 + x4.y * w1 + x4.z * w2 + x4.w * w3;
        }
    }
    float bias = WB_b[c];
    #pragma unroll
    for (int k = 0; k < 16; k++) {
        int r = rg * 16 + k;
        g_zB[(size_t)(row0 + r) * 128 + c] = acc[k] + bias;
    }
}

// ---------------- K4: partial masked softmax-attention (m-split by 8) ----------------
// CTA = 64 rows x 8 heads, 256 threads; warp = head, each thread 2 rows.
// grid.x = 256: tile = x>>3 (n-tile of 64), s = x&7 (m eighth). grid.y = b.
#define MAIN_SMEM ((8192 + 2048) * 4 + 64 * 8)
__global__ __launch_bounds__(256, 2)
void k_main(const int* __restrict__ mask) {
    extern __shared__ float sm[];
    float*  zB_s  = sm;                       // 8192 f
    float4* eBp_s = (float4*)(sm + 8192);     // 512 float4: [h][64]
    ull*    mp_s  = (ull*)(sm + 8192 + 2048); // 64

    int t = threadIdx.x;
    int lane = t & 31;                        // row within tile (and +32)
    int h = t >> 5;                           // head
    int b = blockIdx.y;
    int tile = blockIdx.x >> 3;
    int s = blockIdx.x & 7;
    int n0 = tile * 64;
    int row0 = b * NA + n0;
    int mlo = s * (NBB / NSPLIT);             // 256-wide m range

    float4 pa0 = g_eAp[(size_t)(row0 + lane) * 8 + h];      // (ea, p0, p1, -)
    float4 pa1 = g_eAp[(size_t)(row0 + lane + 32) * 8 + h];
    float nea0 = -pa0.x, pA00 = pa0.y, pA01 = pa0.z;        // sign test: eb >= -ea
    float nea1 = -pa1.x, pA10 = pa1.y, pA11 = pa1.z;

    ull acc0[8], acc1[8];
    #pragma unroll
    for (int k = 0; k < 8; k++) { acc0[k] = 0ULL; acc1[k] = 0ULL; }
    ull accZ = 0ULL;                          // packed (Z0, Z1)
    const ull ONES2 = 0x3F8000003F800000ULL;  // (1.0f, 1.0f)

    const float4* eBbase = g_eBp + ((size_t)b * 8) * 2048;  // + h*2048 + m

    for (int m0 = mlo; m0 < mlo + NBB / NSPLIT; m0 += 64) {
        __syncthreads();
        // stage zB tile (64 rows x 128 f = 2048 float4), 8 per thread
        {
            const float4* src = (const float4*)(g_zB + (size_t)(b * NBB + m0) * 128);
            #pragma unroll
            for (int j = 0; j < 8; j++)
                ((float4*)zB_s)[t + j * 256] = src[t + j * 256];
        }
        // stage eBp tile: [h][64] float4, 2 per thread
        {
            int hh = t >> 6, mm = t & 63;
            eBp_s[hh * 64 + mm]       = eBbase[(size_t)hh * 2048 + m0 + mm];
            eBp_s[(hh + 4) * 64 + mm] = eBbase[(size_t)(hh + 4) * 2048 + m0 + mm];
        }
        // pack mask (int32 0/1): 64 rows x 64 bits = 512 bytes, 2 per thread
        {
            #pragma unroll
            for (int j = 0; j < 2; j++) {
                int idx = t + j * 256;
                int rowi = idx >> 3, bytei = idx & 7;
                const int4* mp4 = (const int4*)
                    (mask + ((size_t)(row0 + rowi)) * NBB + m0 + bytei * 8);
                int4 a = mp4[0], c = mp4[1];
                unsigned int bits =
                      (unsigned int)(a.x != 0)
                    | ((unsigned int)(a.y != 0) << 1)
                    | ((unsigned int)(a.z != 0) << 2)
                    | ((unsigned int)(a.w != 0) << 3)
                    | ((unsigned int)(c.x != 0) << 4)
                    | ((unsigned int)(c.y != 0) << 5)
                    | ((unsigned int)(c.z != 0) << 6)
                    | ((unsigned int)(c.w != 0) << 7);
                ((unsigned char*)mp_s)[rowi * 8 + bytei] = (unsigned char)bits;
            }
        }
        __syncthreads();

        ull mb0 = mp_s[lane];
        ull mb1 = mp_s[lane + 32];
        const float4* ebh = eBp_s + h * 64;
        #pragma unroll 8
        for (int m = 0; m < 64; m++) {
            float4 eb = ebh[m];                         // (eb, pB0, pB1, -)
            float w0 = (eb.x >= nea0) ? (pA00 * eb.y) : (pA01 * eb.z);
            float w1 = (eb.x >= nea1) ? (pA10 * eb.y) : (pA11 * eb.z);
            w0 = ((mb0 >> m) & 1ULL) ? w0 : 0.f;
            w1 = ((mb1 >> m) & 1ULL) ? w1 : 0.f;
            ull wz, wd0, wd1;
            PACK2(wz, w0, w1);
            FMA2(accZ, wz, ONES2);                      // Z0 += w0, Z1 += w1
            PACK2(wd0, w0, w0);
            PACK2(wd1, w1, w1);
            const ulonglong2* z = (const ulonglong2*)(zB_s + m * 128 + h * 16);
            ulonglong2 q0 = z[0], q1 = z[1], q2 = z[2], q3 = z[3];
            FMA2(acc0[0], wd0, q0.x); FMA2(acc0[1], wd0, q0.y);
            FMA2(acc0[2], wd0, q1.x); FMA2(acc0[3], wd0, q1.y);
            FMA2(acc0[4], wd0, q2.x); FMA2(acc0[5], wd0, q2.y);
            FMA2(acc0[6], wd0, q3.x); FMA2(acc0[7], wd0, q3.y);
            FMA2(acc1[0], wd1, q0.x); FMA2(acc1[1], wd1, q0.y);
            FMA2(acc1[2], wd1, q1.x); FMA2(acc1[3], wd1, q1.y);
            FMA2(acc1[4], wd1, q2.x); FMA2(acc1[5], wd1, q2.y);
            FMA2(acc1[6], wd1, q3.x); FMA2(acc1[7], wd1, q3.y);
        }
    }

    // write partials, n-major coalesced: [s][b][h][d2][n] packed ull
    {
        float Z0, Z1;
        UNPACK2(Z0, Z1, accZ);
        size_t base = ((((size_t)s * BB + b) * HH + h) * 8) * NA + n0 + lane;
        #pragma unroll
        for (int k = 0; k < 8; k++) {
            g_PaccU[base + (size_t)k * NA]      = acc0[k];
            g_PaccU[base + (size_t)k * NA + 32] = acc1[k];
        }
        size_t zbase = (((size_t)s * BB + b) * HH + h) * NA + n0 + lane;
        g_PZ[zbase]      = Z0;
        g_PZ[zbase + 32] = Z1;
    }
}

// ---------------- K5: combine partials + normalize + output GEMM ----------------
// CTA = 32 rows x 8 heads = 256 threads; grid (64, 4)
#define RED_SMEM ((16384 + 32 * 129) * 4)
__global__ __launch_bounds__(256)
void k_reduce(const float* __restrict__ W_b, float* __restrict__ out) {
    extern __shared__ float rsm[];
    float* W_Ts = rsm;                  // 16384
    float* cat_s = rsm + 16384;         // 32*129
    int t = threadIdx.x;
    int lane = t & 31;
    int h = t >> 5;
    int b = blockIdx.y;
    int n0 = blockIdx.x * 32;
    int n = n0 + lane;
    int row = b * NA + n;

    #pragma unroll
    for (int j = 0; j < 16; j++)
        ((float4*)W_Ts)[t + j * 256] = ((const float4*)g_WT)[t + j * 256];

    {
        ull v[8];
        #pragma unroll
        for (int k = 0; k < 8; k++) v[k] = 0ULL;
        float Z = 0.f;
        const ull ONES2 = 0x3F8000003F800000ULL;
        #pragma unroll
        for (int sp = 0; sp < NSPLIT; sp++) {
            size_t base = ((((size_t)sp * BB + b) * HH + h) * 8) * NA + n;
            #pragma unroll
            for (int k = 0; k < 8; k++)
                FMA2(v[k], g_PaccU[base + (size_t)k * NA], ONES2);
            Z += g_PZ[(((size_t)sp * BB + b) * HH + h) * NA + n];
        }
        float inv = 1.f / Z;
        #pragma unroll
        for (int k = 0; k < 8; k++) {
            float lo, hi;
            UNPACK2(lo, hi, v[k]);
            cat_s[lane * 129 + h * 16 + 2 * k]     = lo * inv;
            cat_s[lane * 129 + h * 16 + 2 * k + 1] = hi * inv;
        }
    }
    __syncthreads();

    float acc2[16];
    {
        const float4* wb4 = (const float4*)(W_b + h * 16);
        float4 b0 = __ldg(wb4), b1 = __ldg(wb4 + 1), b2 = __ldg(wb4 + 2), b3 = __ldg(wb4 + 3);
        acc2[0]  = b0.x; acc2[1]  = b0.y; acc2[2]  = b0.z; acc2[3]  = b0.w;
        acc2[4]  = b1.x; acc2[5]  = b1.y; acc2[6]  = b1.z; acc2[7]  = b1.w;
        acc2[8]  = b2.x; acc2[9]  = b2.y; acc2[10] = b2.z; acc2[11] = b2.w;
        acc2[12] = b3.x; acc2[13] = b3.y; acc2[14] = b3.z; acc2[15] = b3.w;
    }
    for (int c = 0; c < 128; c++) {
        float x = cat_s[lane * 129 + c];
        const float4* w4 = (const float4*)(W_Ts + c * 128 + h * 16);
        float4 w0 = w4[0], w1 = w4[1], w2 = w4[2], w3 = w4[3];
        acc2[0]  += x * w0.x; acc2[1]  += x * w0.y; acc2[2]  += x * w0.z; acc2[3]  += x * w0.w;
        acc2[4]  += x * w1.x; acc2[5]  += x * w1.y; acc2[6]  += x * w1.z; acc2[7]  += x * w1.w;
        acc2[8]  += x * w2.x; acc2[9]  += x * w2.y; acc2[10] += x * w2.z; acc2[11] += x * w2.w;
        acc2[12] += x * w3.x; acc2[13] += x * w3.y; acc2[14] += x * w3.z; acc2[15] += x * w3.w;
    }
    float4* o4 = (float4*)(out + (size_t)row * 128 + h * 16);
    o4[0] = make_float4(acc2[0],  acc2[1],  acc2[2],  acc2[3]);
    o4[1] = make_float4(acc2[4],  acc2[5],  acc2[6],  acc2[7]);
    o4[2] = make_float4(acc2[8],  acc2[9],  acc2[10], acc2[11]);
    o4[3] = make_float4(acc2[12], acc2[13], acc2[14], acc2[15]);
}

// ---------------- launcher ----------------
extern "C" void kernel_launch(void* const* d_in, const int* in_sizes, int n_in,
                              void* d_out, int out_size) {
    (void)in_sizes; (void)n_in; (void)out_size;
    const float* h_A  = (const float*)d_in[0];
    const float* h_B  = (const float*)d_in[1];
    const int*   mask = (const int*)d_in[2];
    const float* WA_w = (const float*)d_in[3];
    const float* WA_b = (const float*)d_in[4];
    const float* WB_w = (const float*)d_in[5];
    const float* WB_b = (const float*)d_in[6];
    const float* aA_w = (const float*)d_in[7];
    const float* aA_b = (const float*)d_in[8];
    const float* aB_w = (const float*)d_in[9];
    const float* aB_b = (const float*)d_in[10];
    const float* W_w  = (const float*)d_in[11];
    const float* W_b  = (const float*)d_in[12];
    float* out = (float*)d_out;

    cudaFuncSetAttribute(k_zB,     cudaFuncAttributeMaxDynamicSharedMemorySize, ZB_SMEM);
    cudaFuncSetAttribute(k_main,   cudaFuncAttributeMaxDynamicSharedMemorySize, MAIN_SMEM);
    cudaFuncSetAttribute(k_reduce, cudaFuncAttributeMaxDynamicSharedMemorySize, RED_SMEM);

    k_e<<<576, 256>>>(h_A, h_B, WA_w, WA_b, aA_w, aA_b, WB_w, WB_b, aB_w, aB_b, W_w);
    k_zB<<<256, 256, ZB_SMEM>>>(h_B, WB_w, WB_b);
    k_main<<<dim3(32 * NSPLIT, 4), 256, MAIN_SMEM>>>(mask);
    k_reduce<<<dim3(64, 4), 256, RED_SMEM>>>(W_b, out);
}